// round 16
// baseline (speedup 1.0000x reference)
#include <cuda_runtime.h>
#include <cuda_fp16.h>
#include <math.h>

#define BB 2
#define NQ 256
#define NK 2048
#define DIM 256
#define NH 8
#define HD 32
#define NPTS 8
#define NCELL 1000

#define SST (NK + 8)             // padded score row stride (floats)

typedef unsigned long long ull;
#define FMA_F32X2(d, a, b, c) \
    asm("fma.rn.f32x2 %0, %1, %2, %3;" : "=l"(d) : "l"(a), "l"(b), "l"(c))
#define PACK2(d, lo, hi) \
    asm("mov.b64 %0, {%1, %2};" : "=l"(d) : "f"(lo), "f"(hi))

union f4u { float4 f; ull u[2]; };
union u2f { ull u; float f[2]; };

// scratch (device globals — no allocation allowed)
__device__ __half g_tables[NPTS * NCELL * NH];  // [i][cell=z*100+y*10+x][h], fp16
__device__ float g_qproj[BB * NQ * DIM];
__device__ float g_kproj[BB * NK * HD];
__device__ float g_vproj[BB * NK * HD];
__device__ float g_xmid [BB * NQ * DIM];
__device__ float g_scores[(size_t)BB * NQ * NH * NK];   // raw RPE  [bq*8+h][k]
__device__ float g_qk[(size_t)BB * NQ * NH * NK];       // QK^T     [bq*8+h][k]

// -------------------- merged pre kernel: tables | qproj | kvproj ------------
// blocks [0,256): tables, [256,512): qproj, [512,1536): kvproj. 256 threads.
__global__ void k_pre(const float* __restrict__ w1, const float* __restrict__ b1,
                      const float* __restrict__ w2,
                      const float* __restrict__ query, const float* __restrict__ qw,
                      const float* __restrict__ qb,
                      const float* __restrict__ key,
                      const float* __restrict__ kw, const float* __restrict__ kb,
                      const float* __restrict__ vw, const float* __restrict__ vb) {
    __shared__ float sm[1536];
    int blk = blockIdx.x;
    int t = threadIdx.x;

    if (blk < 256) {
        // ---- CPB tables: blk = i(8) x chunk(32) ----
        float* s_w1 = sm;            // 384
        float* s_b1 = sm + 384;      // 128
        float* s_w2 = sm + 512;      // 1024
        int i = blk >> 5, chunk = blk & 31;
        {
            const float* w1i = w1 + i * 384;
            const float* w2i = w2 + i * 1024;
            if (t < 128) { s_w1[t] = w1i[t]; s_w1[128 + t] = w1i[128 + t]; s_w1[256 + t] = w1i[256 + t]; s_b1[t] = b1[i * 128 + t]; }
            s_w2[t] = w2i[t];
            s_w2[256 + t] = w2i[256 + t];
            s_w2[512 + t] = w2i[512 + t];
            s_w2[768 + t] = w2i[768 + t];
        }
        __syncthreads();
        int cell = chunk * 32 + (t >> 3);
        int h = t & 7;
        if (cell >= NCELL) return;
        int p = cell / 100, q = (cell / 10) % 10, r = cell % 10;
        const float step = 8.0f / 9.0f;
        float lp = -4.0f + p * step, lq = -4.0f + q * step, lr = -4.0f + r * step;
        float acc = 0.f;
        #pragma unroll 8
        for (int d = 0; d < 128; d++) {
            float hv = fmaf(lp, s_w1[d], fmaf(lq, s_w1[128 + d], fmaf(lr, s_w1[256 + d], s_b1[d])));
            hv = fmaxf(hv, 0.0f);
            acc = fmaf(hv, s_w2[d * 8 + h], acc);
        }
        g_tables[(i * NCELL + cell) * NH + h] = __float2half(acc);
    } else if (blk < 512) {
        // ---- Q projection: 2 rows/block ----
        float* rows0 = sm;           // 256
        float* rows1 = sm + 256;     // 256
        int bq2 = blk - 256;         // b*128 + qpair
        int b = bq2 >> 7, qbase = (bq2 & 127) * 2;
        rows0[t] = query[((qbase + 0) * BB + b) * DIM + t];
        rows1[t] = query[((qbase + 1) * BB + b) * DIM + t];
        __syncthreads();
        float bj = qb[t];
        float a0 = bj, a1 = bj;
        #pragma unroll 4
        for (int c = 0; c < DIM; c++) {
            float wv = qw[c * DIM + t];
            a0 += rows0[c] * wv;
            a1 += rows1[c] * wv;
        }
        g_qproj[((b << 8) + qbase + 0) * DIM + t] = a0;
        g_qproj[((b << 8) + qbase + 1) * DIM + t] = a1;
    } else {
        // ---- K/V projection: 4 rows/block, 8 warps ----
        float (*rows)[DIM] = (float(*)[DIM])sm;   // 4 x 256
        int kb2 = blk - 512;         // b*512 + kgroup
        int b = kb2 >> 9, kbase = (kb2 & 511) * 4;
        {
            int r = t >> 6, cbase = (t & 63) * 4;
            *(float4*)&rows[r][cbase] = *(const float4*)&key[((kbase + r) * BB + b) * DIM + cbase];
        }
        __syncthreads();
        int warp = t >> 5;
        int j = t & 31;
        int r = warp >> 1;
        int which = warp & 1;
        const float* w = which ? vw : kw;
        float acc = which ? vb[j] : kb[j];
        #pragma unroll 4
        for (int c = 0; c < DIM; c++)
            acc += rows[r][c] * w[c * HD + j];
        float* dst = which ? g_vproj : g_kproj;
        dst[(b * NK + kbase + r) * HD + j] = acc;
    }
}

// -------------------- RPE helpers --------------------
__device__ __forceinline__ float xform(float dd) {
    float g = __log2f(fabsf(dd) * 512.0f + 1.0f) * (1.0f / 12.0f);
    return copysignf(g, dd);
}

__device__ __forceinline__ void axis_setup(float f, int scale, int* o, float* w) {
    float f0 = floorf(f);
    int i0 = (int)f0;
    float w1 = f - f0;
    int c0 = min(max(i0, 0), 9);
    int c1 = min(max(i0 + 1, 0), 9);
    o[0] = c0 * scale;
    o[1] = c1 * scale;
    w[0] = ((unsigned)i0 < 10u) ? 1.0f - w1 : 0.0f;
    w[1] = ((unsigned)(i0 + 1) < 10u) ? w1 : 0.0f;
}

// -------------------- merged RPE + QK kernel, 4 CTAs/SM ----------------------
// blocks [0,1024): RPE (bq = blk>>1, kh = blk&1), 4 stages x 2 tables, 32 KB smem
// blocks [1024,3072): QK 64x64 tiles, thread = 4r x 4k, writes g_qk
#define RPE_THREADS 256
#define RPE_KPT 4
#define TBL_HALVES_PER_STAGE (2 * NCELL * NH)      // 16000 halves = 32000 B
#define RPEQK_SMEM 32000

__global__ void __launch_bounds__(RPE_THREADS, 4)
k_rpeqk(const float* __restrict__ refpt, const float* __restrict__ xyz) {
    extern __shared__ char smraw[];
    int t = threadIdx.x;
    int blk = blockIdx.x;

    if (blk < 1024) {
        // ================= RPE path =================
        __half* s_tblr = (__half*)smraw;           // 16000 halves
        __shared__ float s_rp[24];
        int kh = blk & 1;
        int bq = blk >> 1;
        int b = bq >> 8;

        if (t < 24) s_rp[t] = refpt[bq * 24 + t];

        __half2 hacc[RPE_KPT][4];
        #pragma unroll
        for (int m = 0; m < RPE_KPT; m++)
            #pragma unroll
            for (int j = 0; j < 4; j++) hacc[m][j] = __float2half2_rn(0.f);

        #pragma unroll 1
        for (int stage = 0; stage < 4; stage++) {
            __syncthreads();
            {
                const uint4* src = (const uint4*)g_tables + stage * (TBL_HALVES_PER_STAGE / 8);
                uint4* dst = (uint4*)s_tblr;
                #pragma unroll 1
                for (int idx = t; idx < TBL_HALVES_PER_STAGE / 8; idx += RPE_THREADS)
                    dst[idx] = src[idx];
            }
            __syncthreads();

            #pragma unroll 1
            for (int m = 0; m < RPE_KPT; m++) {
                int k = kh * 1024 + m * RPE_THREADS + t;
                const float* xv = xyz + (b * NK + k) * 3;
                float kx = xv[0], ky = xv[1], kz = xv[2];
                #pragma unroll
                for (int ii = 0; ii < 2; ii++) {
                    int i = stage * 2 + ii;
                    float gx = xform(s_rp[i*3+0] - kx);
                    float gy = xform(s_rp[i*3+1] - ky);
                    float gz = xform(s_rp[i*3+2] - kz);
                    float fx = fmaf(gx, 4.5f, 4.5f);
                    float fy = fmaf(gy, 4.5f, 4.5f);
                    float fz = fmaf(gz, 4.5f, 4.5f);
                    int oxa[2], oya[2], oza[2];
                    float wxa[2], wya[2], wza[2];
                    axis_setup(fx, NH,       oxa, wxa);
                    axis_setup(fy, NH * 10,  oya, wya);
                    axis_setup(fz, NH * 100, oza, wza);
                    float wzy[4] = {wza[0]*wya[0], wza[0]*wya[1], wza[1]*wya[0], wza[1]*wya[1]};
                    int ozy[4];
                    ozy[0] = oza[0]+oya[0]; ozy[1] = oza[0]+oya[1];
                    ozy[2] = oza[1]+oya[0]; ozy[3] = oza[1]+oya[1];
                    const __half* base = s_tblr + ii * (NCELL * NH);
                    #pragma unroll
                    for (int hb = 0; hb < 2; hb++) {
                        uint4 raw[4];
                        #pragma unroll
                        for (int c = 0; c < 4; c++)
                            raw[c] = *(const uint4*)(base + ozy[hb * 2 + (c >> 1)] + oxa[c & 1]);
                        #pragma unroll
                        for (int c = 0; c < 4; c++) {
                            float w = wzy[hb * 2 + (c >> 1)] * wxa[c & 1];
                            __half2 wh = __float2half2_rn(w);
                            hacc[m][0] = __hfma2(wh, *(const __half2*)&raw[c].x, hacc[m][0]);
                            hacc[m][1] = __hfma2(wh, *(const __half2*)&raw[c].y, hacc[m][1]);
                            hacc[m][2] = __hfma2(wh, *(const __half2*)&raw[c].z, hacc[m][2]);
                            hacc[m][3] = __hfma2(wh, *(const __half2*)&raw[c].w, hacc[m][3]);
                        }
                    }
                }
            }
        }

        // write raw RPE: g_scores[bq*8h rows][k]
        #pragma unroll
        for (int m = 0; m < RPE_KPT; m++) {
            int k = kh * 1024 + m * RPE_THREADS + t;
            float* sp = g_scores + (size_t)bq * NH * NK + k;
            float2 f0 = __half22float2(hacc[m][0]);
            float2 f1 = __half22float2(hacc[m][1]);
            float2 f2 = __half22float2(hacc[m][2]);
            float2 f3 = __half22float2(hacc[m][3]);
            sp[0 * NK] = f0.x; sp[1 * NK] = f0.y;
            sp[2 * NK] = f1.x; sp[3 * NK] = f1.y;
            sp[4 * NK] = f2.x; sp[5 * NK] = f2.y;
            sp[6 * NK] = f3.x; sp[7 * NK] = f3.y;
        }
    } else {
        // ================= QK path: 64x64 tile, thread = 4r x 4k =============
        float* As = (float*)smraw;                 // 64 x 36 (padded)
        float* Bs = (float*)smraw + 64 * 36;       // 64 x 32
        int blk2 = blk - 1024;                     // kt(32) | rt(32) | b(2)
        int kt = blk2 & 31;
        int rt = (blk2 >> 5) & 31;
        int b  = blk2 >> 10;
        int r0 = rt * 64, k0 = kt * 64;
        const float scale = 0.17677669529663687f;

        #pragma unroll
        for (int idx = t; idx < 512; idx += RPE_THREADS) {
            int r = idx >> 3, d4 = idx & 7;
            float4 v = *(const float4*)(g_qproj + ((size_t)(b * 2048 + r0 + r)) * 32 + d4 * 4);
            v.x *= scale; v.y *= scale; v.z *= scale; v.w *= scale;
            *(float4*)&As[r * 36 + d4 * 4] = v;
        }
        #pragma unroll
        for (int idx = t; idx < 512; idx += RPE_THREADS) {
            int r = idx >> 3, d4 = idx & 7;
            *(float4*)&Bs[r * 32 + d4 * 4] =
                *(const float4*)(g_kproj + ((size_t)(b * NK + k0 + r)) * 32 + d4 * 4);
        }
        __syncthreads();

        int tr = t & 15;        // r sub-tile (rows tr + 16*i)
        int tk = t >> 4;        // k sub-tile (cols tk*4 + j)
        float acc[4][4];
        #pragma unroll
        for (int i = 0; i < 4; i++)
            #pragma unroll
            for (int j = 0; j < 4; j++) acc[i][j] = 0.f;

        #pragma unroll
        for (int d4 = 0; d4 < 8; d4++) {
            float4 bf[4];
            #pragma unroll
            for (int j = 0; j < 4; j++)
                bf[j] = *(const float4*)&Bs[(tk * 4 + j) * 32 + d4 * 4];
            #pragma unroll
            for (int i = 0; i < 4; i++) {
                float4 a = *(const float4*)&As[(tr + 16 * i) * 36 + d4 * 4];
                #pragma unroll
                for (int j = 0; j < 4; j++)
                    acc[i][j] += a.x * bf[j].x + a.y * bf[j].y + a.z * bf[j].z + a.w * bf[j].w;
            }
        }

        #pragma unroll
        for (int i = 0; i < 4; i++) {
            float4 o = {acc[i][0], acc[i][1], acc[i][2], acc[i][3]};
            *(float4*)&g_qk[((size_t)(b * 2048 + r0 + tr + 16 * i)) * NK + k0 + tk * 4] = o;
        }
    }
}

// -------------------- softmax + AV kernel --------------------
#define SOFT_THREADS 512
#define SMS_RED    (NH * SST)                    // 16448
#define SMS_TOTAL  (SMS_RED + 512)               // 16960 floats
#define PART_STRIDE 264

__global__ void __launch_bounds__(SOFT_THREADS, 2)
k_soft(float* __restrict__ out_attn) {
    extern __shared__ float sms[];
    float* s_scores = sms;
    float* s_red    = sms + SMS_RED;

    int t = threadIdx.x;
    int bq = blockIdx.x;
    int b = bq >> 8, nq = bq & 255;

    // ---- load logits = RPE + QK (float4, k = 4t) + running max ----
    float runmax[NH];
    const float* grp = g_scores + (size_t)bq * NH * NK + 4 * t;
    const float* gqk = g_qk     + (size_t)bq * NH * NK + 4 * t;
    #pragma unroll
    for (int h = 0; h < NH; h++) {
        float4 a = *(const float4*)(grp + h * NK);
        float4 qv = *(const float4*)(gqk + h * NK);
        a.x += qv.x; a.y += qv.y; a.z += qv.z; a.w += qv.w;
        *(float4*)&s_scores[h * SST + 4 * t] = a;
        runmax[h] = fmaxf(fmaxf(a.x, a.y), fmaxf(a.z, a.w));
    }

    // ---- block max ----
    int lane = t & 31, wid = t >> 5;  // 16 warps
    #pragma unroll
    for (int h = 0; h < NH; h++) {
        float v = runmax[h];
        #pragma unroll
        for (int o = 16; o; o >>= 1) v = fmaxf(v, __shfl_xor_sync(0xffffffffu, v, o));
        if (lane == 0) s_red[h * 16 + wid] = v;
    }
    __syncthreads();
    if (t < NH) {
        float v = s_red[t * 16];
        for (int w2 = 1; w2 < 16; w2++) v = fmaxf(v, s_red[t * 16 + w2]);
        s_red[128 + t] = v;
    }
    __syncthreads();

    // ---- exp sweep (float4) ----
    #pragma unroll
    for (int h = 0; h < NH; h++) {
        float mh = s_red[128 + h];
        float4* p = (float4*)&s_scores[h * SST + 4 * t];
        float4 v = *p;
        v.x = __expf(v.x - mh); v.y = __expf(v.y - mh);
        v.z = __expf(v.z - mh); v.w = __expf(v.w - mh);
        *p = v;
        float s = (v.x + v.y) + (v.z + v.w);
        #pragma unroll
        for (int o = 16; o; o >>= 1) s += __shfl_xor_sync(0xffffffffu, s, o);
        if (lane == 0) s_red[h * 16 + wid] = s;
    }
    __syncthreads();
    if (t < NH) {
        float v = 0.f;
        for (int w2 = 0; w2 < 16; w2++) v += s_red[t * 16 + w2];
        s_red[136 + t] = 1.0f / v;
    }
    __syncthreads();

    // ---- normalized attn writeback (float4) ----
    #pragma unroll
    for (int h = 0; h < NH; h++) {
        float r = s_red[136 + h];
        float4 v = *(const float4*)&s_scores[h * SST + 4 * t];
        v.x *= r; v.y *= r; v.z *= r; v.w *= r;
        *(float4*)&out_attn[((size_t)(b * NH + h) * NQ + nq) * NK + 4 * t] = v;
    }

    // ---- AV: thread = (hg 0..1, ks 0..31, dg 0..7), 4 heads/thread ----
    ull acc01[4], acc23[4];
    #pragma unroll
    for (int hh = 0; hh < 4; hh++) { acc01[hh] = 0ull; acc23[hh] = 0ull; }
    int hg  = t >> 8;
    int rem = t & 255;
    int ks  = rem >> 3;          // 0..31, 64 k each
    int dg  = rem & 7;
    {
        const float* vb = g_vproj + (size_t)b * NK * HD + dg * 4;
        int kbase = ks * 64;
        #pragma unroll 1
        for (int kk4 = 0; kk4 < 16; kk4++) {
            int k = kbase + kk4 * 4;
            f4u v0, v1, v2, v3;
            v0.f = *(const float4*)(vb + (k + 0) * HD);
            v1.f = *(const float4*)(vb + (k + 1) * HD);
            v2.f = *(const float4*)(vb + (k + 2) * HD);
            v3.f = *(const float4*)(vb + (k + 3) * HD);
            #pragma unroll
            for (int hh = 0; hh < 4; hh++) {
                int h = hg * 4 + hh;
                float4 p = *(const float4*)&s_scores[h * SST + k];
                ull pp;
                PACK2(pp, p.x, p.x);
                FMA_F32X2(acc01[hh], pp, v0.u[0], acc01[hh]);
                FMA_F32X2(acc23[hh], pp, v0.u[1], acc23[hh]);
                PACK2(pp, p.y, p.y);
                FMA_F32X2(acc01[hh], pp, v1.u[0], acc01[hh]);
                FMA_F32X2(acc23[hh], pp, v1.u[1], acc23[hh]);
                PACK2(pp, p.z, p.z);
                FMA_F32X2(acc01[hh], pp, v2.u[0], acc01[hh]);
                FMA_F32X2(acc23[hh], pp, v2.u[1], acc23[hh]);
                PACK2(pp, p.w, p.w);
                FMA_F32X2(acc01[hh], pp, v3.u[0], acc01[hh]);
                FMA_F32X2(acc23[hh], pp, v3.u[1], acc23[hh]);
            }
        }
    }
    __syncthreads();    // scores now dead — overlay partials

    #pragma unroll
    for (int hh = 0; hh < 4; hh++) {
        int h = hg * 4 + hh;
        u2f lo, hi; lo.u = acc01[hh]; hi.u = acc23[hh];
        float4 o = {lo.f[0], lo.f[1], hi.f[0], hi.f[1]};
        *(float4*)&s_scores[ks * PART_STRIDE + h * 32 + dg * 4] = o;
    }
    __syncthreads();
    if (t < 256) {
        int h = t >> 5;
        float acc = 0.f;
        #pragma unroll 8
        for (int ks2 = 0; ks2 < 32; ks2++) acc += s_scores[ks2 * PART_STRIDE + t];
        acc *= s_red[136 + h];
        g_xmid[bq * DIM + t] = acc;
    }
}

// -------------------- output projection: (qpair, j-half), 512 blocks, 128 thr --
__global__ void k_proj(const float* __restrict__ w, const float* __restrict__ bias,
                       float* __restrict__ out_x) {
    __shared__ float rows[2][DIM];
    int blk = blockIdx.x;               // (b*128 + qpair)*2 + jh
    int jh = blk & 1;
    int rp = blk >> 1;
    int b = rp >> 7, qbase = (rp & 127) * 2;
    int t = threadIdx.x;                // 128
    int j = jh * 128 + t;
    // stage both x rows (each thread loads 2 elements per row half)
    rows[0][t]       = g_xmid[((b << 8) + qbase + 0) * DIM + t];
    rows[0][t + 128] = g_xmid[((b << 8) + qbase + 0) * DIM + t + 128];
    rows[1][t]       = g_xmid[((b << 8) + qbase + 1) * DIM + t];
    rows[1][t + 128] = g_xmid[((b << 8) + qbase + 1) * DIM + t + 128];
    __syncthreads();
    float bj = bias[j];
    float a0 = bj, a1 = bj;
    #pragma unroll 16
    for (int c = 0; c < DIM; c++) {
        float wv = w[c * DIM + j];
        a0 += rows[0][c] * wv;
        a1 += rows[1][c] * wv;
    }
    out_x[((qbase + 0) * BB + b) * DIM + j] = a0;
    out_x[((qbase + 1) * BB + b) * DIM + j] = a1;
}

// -------------------- launch --------------------
extern "C" void kernel_launch(void* const* d_in, const int* in_sizes, int n_in,
                              void* d_out, int out_size) {
    const float* query = (const float*)d_in[0];
    const float* key   = (const float*)d_in[1];
    const float* refpt = (const float*)d_in[2];
    const float* xyz   = (const float*)d_in[4];
    const float* q_w   = (const float*)d_in[5];
    const float* q_b   = (const float*)d_in[6];
    const float* k_w   = (const float*)d_in[7];
    const float* k_b   = (const float*)d_in[8];
    const float* v_w   = (const float*)d_in[9];
    const float* v_b   = (const float*)d_in[10];
    const float* p_w   = (const float*)d_in[11];
    const float* p_b   = (const float*)d_in[12];
    const float* w1    = (const float*)d_in[13];
    const float* b1    = (const float*)d_in[14];
    const float* w2    = (const float*)d_in[15];

    float* out_x    = (float*)d_out;                       // (nQ, B, DIM)
    float* out_attn = (float*)d_out + BB * NQ * DIM;       // (B, NH, nQ, nK)

    const int soft_smem = SMS_TOTAL * (int)sizeof(float);  // 67840 B
    cudaFuncSetAttribute(k_rpeqk, cudaFuncAttributeMaxDynamicSharedMemorySize, RPEQK_SMEM);
    cudaFuncSetAttribute(k_soft,  cudaFuncAttributeMaxDynamicSharedMemorySize, soft_smem);

    k_pre   <<<1536, 256>>>(w1, b1, w2, query, q_w, q_b, key, k_w, k_b, v_w, v_b);
    k_rpeqk <<<1024 + 2048, RPE_THREADS, RPEQK_SMEM>>>(refpt, xyz);
    k_soft  <<<BB * NQ, SOFT_THREADS, soft_smem>>>(out_attn);
    k_proj  <<<BB * NQ, 128>>>(p_w, p_b, out_x);
}

// round 17
// speedup vs baseline: 1.1782x; 1.1782x over previous
#include <cuda_runtime.h>
#include <cuda_fp16.h>
#include <math.h>

#define BB 2
#define NQ 256
#define NK 2048
#define DIM 256
#define NH 8
#define HD 32
#define NPTS 8
#define NCELL 1000

#define SST (NK + 8)             // padded score row stride (floats)

typedef unsigned long long ull;
#define FMA_F32X2(d, a, b, c) \
    asm("fma.rn.f32x2 %0, %1, %2, %3;" : "=l"(d) : "l"(a), "l"(b), "l"(c))
#define PACK2(d, lo, hi) \
    asm("mov.b64 %0, {%1, %2};" : "=l"(d) : "f"(lo), "f"(hi))

union f4u { float4 f; ull u[2]; };
union u2f { ull u; float f[2]; };

// scratch (device globals — no allocation allowed)
__device__ __half g_tables[NPTS * NCELL * NH];  // [i][cell=z*100+y*10+x][h], fp16
__device__ float g_qproj[BB * NQ * DIM];
__device__ float g_kproj[BB * NK * HD];
__device__ float g_vproj[BB * NK * HD];
__device__ float g_xmid [BB * NQ * DIM];
__device__ float g_scores[(size_t)BB * NQ * NH * NK];   // raw RPE  [bq*8+h][k]
__device__ float g_qk[(size_t)BB * NQ * NH * NK];       // QK^T     [bq*8+h][k]

// -------------------- merged pre kernel: tables | qproj | kvproj ------------
// blocks [0,256): tables, [256,512): qproj, [512,1536): kvproj. 256 threads.
__global__ void k_pre(const float* __restrict__ w1, const float* __restrict__ b1,
                      const float* __restrict__ w2,
                      const float* __restrict__ query, const float* __restrict__ qw,
                      const float* __restrict__ qb,
                      const float* __restrict__ key,
                      const float* __restrict__ kw, const float* __restrict__ kb,
                      const float* __restrict__ vw, const float* __restrict__ vb) {
    __shared__ float sm[1536];
    int blk = blockIdx.x;
    int t = threadIdx.x;

    if (blk < 256) {
        // ---- CPB tables: blk = i(8) x chunk(32) ----
        float* s_w1 = sm;            // 384
        float* s_b1 = sm + 384;      // 128
        float* s_w2 = sm + 512;      // 1024
        int i = blk >> 5, chunk = blk & 31;
        {
            const float* w1i = w1 + i * 384;
            const float* w2i = w2 + i * 1024;
            if (t < 128) { s_w1[t] = w1i[t]; s_w1[128 + t] = w1i[128 + t]; s_w1[256 + t] = w1i[256 + t]; s_b1[t] = b1[i * 128 + t]; }
            s_w2[t] = w2i[t];
            s_w2[256 + t] = w2i[256 + t];
            s_w2[512 + t] = w2i[512 + t];
            s_w2[768 + t] = w2i[768 + t];
        }
        __syncthreads();
        int cell = chunk * 32 + (t >> 3);
        int h = t & 7;
        if (cell >= NCELL) return;
        int p = cell / 100, q = (cell / 10) % 10, r = cell % 10;
        const float step = 8.0f / 9.0f;
        float lp = -4.0f + p * step, lq = -4.0f + q * step, lr = -4.0f + r * step;
        float acc = 0.f;
        #pragma unroll 8
        for (int d = 0; d < 128; d++) {
            float hv = fmaf(lp, s_w1[d], fmaf(lq, s_w1[128 + d], fmaf(lr, s_w1[256 + d], s_b1[d])));
            hv = fmaxf(hv, 0.0f);
            acc = fmaf(hv, s_w2[d * 8 + h], acc);
        }
        g_tables[(i * NCELL + cell) * NH + h] = __float2half(acc);
    } else if (blk < 512) {
        // ---- Q projection: 2 rows/block ----
        float* rows0 = sm;           // 256
        float* rows1 = sm + 256;     // 256
        int bq2 = blk - 256;         // b*128 + qpair
        int b = bq2 >> 7, qbase = (bq2 & 127) * 2;
        rows0[t] = query[((qbase + 0) * BB + b) * DIM + t];
        rows1[t] = query[((qbase + 1) * BB + b) * DIM + t];
        __syncthreads();
        float bj = qb[t];
        float a0 = bj, a1 = bj;
        #pragma unroll 4
        for (int c = 0; c < DIM; c++) {
            float wv = qw[c * DIM + t];
            a0 += rows0[c] * wv;
            a1 += rows1[c] * wv;
        }
        g_qproj[((b << 8) + qbase + 0) * DIM + t] = a0;
        g_qproj[((b << 8) + qbase + 1) * DIM + t] = a1;
    } else {
        // ---- K/V projection: 4 rows/block, 8 warps ----
        float (*rows)[DIM] = (float(*)[DIM])sm;   // 4 x 256
        int kb2 = blk - 512;         // b*512 + kgroup
        int b = kb2 >> 9, kbase = (kb2 & 511) * 4;
        {
            int r = t >> 6, cbase = (t & 63) * 4;
            *(float4*)&rows[r][cbase] = *(const float4*)&key[((kbase + r) * BB + b) * DIM + cbase];
        }
        __syncthreads();
        int warp = t >> 5;
        int j = t & 31;
        int r = warp >> 1;
        int which = warp & 1;
        const float* w = which ? vw : kw;
        float acc = which ? vb[j] : kb[j];
        #pragma unroll 4
        for (int c = 0; c < DIM; c++)
            acc += rows[r][c] * w[c * HD + j];
        float* dst = which ? g_vproj : g_kproj;
        dst[(b * NK + kbase + r) * HD + j] = acc;
    }
}

// -------------------- RPE helpers --------------------
__device__ __forceinline__ float xform(float dd) {
    float g = __log2f(fabsf(dd) * 512.0f + 1.0f) * (1.0f / 12.0f);
    return copysignf(g, dd);
}

__device__ __forceinline__ void axis_setup(float f, int scale, int* o, float* w) {
    float f0 = floorf(f);
    int i0 = (int)f0;
    float w1 = f - f0;
    int c0 = min(max(i0, 0), 9);
    int c1 = min(max(i0 + 1, 0), 9);
    o[0] = c0 * scale;
    o[1] = c1 * scale;
    w[0] = ((unsigned)i0 < 10u) ? 1.0f - w1 : 0.0f;
    w[1] = ((unsigned)(i0 + 1) < 10u) ? w1 : 0.0f;
}

// -------------------- merged RPE + QK kernel, 4 CTAs/SM ----------------------
// blocks [0,1024): RPE (bq = blk>>1, kh = blk&1), 4 stages x 2 tables, 32 KB smem
// blocks [1024,3072): QK 64x64 tiles, thread = 4r x 4k, writes g_qk
#define RPE_THREADS 256
#define RPE_KPT 4
#define TBL_HALVES_PER_STAGE (2 * NCELL * NH)      // 16000 halves = 32000 B
#define RPEQK_SMEM 32000

__global__ void __launch_bounds__(RPE_THREADS, 4)
k_rpeqk(const float* __restrict__ refpt, const float* __restrict__ xyz) {
    extern __shared__ char smraw[];
    int t = threadIdx.x;
    int blk = blockIdx.x;

    if (blk < 1024) {
        // ================= RPE path =================
        __half* s_tblr = (__half*)smraw;           // 16000 halves
        __shared__ float s_rp[24];
        int kh = blk & 1;
        int bq = blk >> 1;
        int b = bq >> 8;

        if (t < 24) s_rp[t] = refpt[bq * 24 + t];

        __half2 hacc[RPE_KPT][4];
        #pragma unroll
        for (int m = 0; m < RPE_KPT; m++)
            #pragma unroll
            for (int j = 0; j < 4; j++) hacc[m][j] = __float2half2_rn(0.f);

        #pragma unroll 1
        for (int stage = 0; stage < 4; stage++) {
            __syncthreads();
            {
                const uint4* src = (const uint4*)g_tables + stage * (TBL_HALVES_PER_STAGE / 8);
                uint4* dst = (uint4*)s_tblr;
                #pragma unroll 1
                for (int idx = t; idx < TBL_HALVES_PER_STAGE / 8; idx += RPE_THREADS)
                    dst[idx] = src[idx];
            }
            __syncthreads();

            #pragma unroll 1
            for (int m = 0; m < RPE_KPT; m++) {
                int k = kh * 1024 + m * RPE_THREADS + t;
                const float* xv = xyz + (b * NK + k) * 3;
                float kx = xv[0], ky = xv[1], kz = xv[2];
                #pragma unroll
                for (int ii = 0; ii < 2; ii++) {
                    int i = stage * 2 + ii;
                    float gx = xform(s_rp[i*3+0] - kx);
                    float gy = xform(s_rp[i*3+1] - ky);
                    float gz = xform(s_rp[i*3+2] - kz);
                    float fx = fmaf(gx, 4.5f, 4.5f);
                    float fy = fmaf(gy, 4.5f, 4.5f);
                    float fz = fmaf(gz, 4.5f, 4.5f);
                    int oxa[2], oya[2], oza[2];
                    float wxa[2], wya[2], wza[2];
                    axis_setup(fx, NH,       oxa, wxa);
                    axis_setup(fy, NH * 10,  oya, wya);
                    axis_setup(fz, NH * 100, oza, wza);
                    float wzy[4] = {wza[0]*wya[0], wza[0]*wya[1], wza[1]*wya[0], wza[1]*wya[1]};
                    int ozy[4];
                    ozy[0] = oza[0]+oya[0]; ozy[1] = oza[0]+oya[1];
                    ozy[2] = oza[1]+oya[0]; ozy[3] = oza[1]+oya[1];
                    const __half* base = s_tblr + ii * (NCELL * NH);
                    #pragma unroll
                    for (int hb = 0; hb < 2; hb++) {
                        uint4 raw[4];
                        #pragma unroll
                        for (int c = 0; c < 4; c++)
                            raw[c] = *(const uint4*)(base + ozy[hb * 2 + (c >> 1)] + oxa[c & 1]);
                        #pragma unroll
                        for (int c = 0; c < 4; c++) {
                            float w = wzy[hb * 2 + (c >> 1)] * wxa[c & 1];
                            __half2 wh = __float2half2_rn(w);
                            hacc[m][0] = __hfma2(wh, *(const __half2*)&raw[c].x, hacc[m][0]);
                            hacc[m][1] = __hfma2(wh, *(const __half2*)&raw[c].y, hacc[m][1]);
                            hacc[m][2] = __hfma2(wh, *(const __half2*)&raw[c].z, hacc[m][2]);
                            hacc[m][3] = __hfma2(wh, *(const __half2*)&raw[c].w, hacc[m][3]);
                        }
                    }
                }
            }
        }

        // write raw RPE: g_scores[bq*8h rows][k]
        #pragma unroll
        for (int m = 0; m < RPE_KPT; m++) {
            int k = kh * 1024 + m * RPE_THREADS + t;
            float* sp = g_scores + (size_t)bq * NH * NK + k;
            float2 f0 = __half22float2(hacc[m][0]);
            float2 f1 = __half22float2(hacc[m][1]);
            float2 f2 = __half22float2(hacc[m][2]);
            float2 f3 = __half22float2(hacc[m][3]);
            sp[0 * NK] = f0.x; sp[1 * NK] = f0.y;
            sp[2 * NK] = f1.x; sp[3 * NK] = f1.y;
            sp[4 * NK] = f2.x; sp[5 * NK] = f2.y;
            sp[6 * NK] = f3.x; sp[7 * NK] = f3.y;
        }
    } else {
        // ================= QK path: 64x64 tile, thread = 4r x 4k =============
        float* As = (float*)smraw;                 // 64 x 36 (padded)
        float* Bs = (float*)smraw + 64 * 36;       // 64 x 32
        int blk2 = blk - 1024;                     // kt(32) | rt(32) | b(2)
        int kt = blk2 & 31;
        int rt = (blk2 >> 5) & 31;
        int b  = blk2 >> 10;
        int r0 = rt * 64, k0 = kt * 64;
        const float scale = 0.17677669529663687f;

        #pragma unroll
        for (int idx = t; idx < 512; idx += RPE_THREADS) {
            int r = idx >> 3, d4 = idx & 7;
            float4 v = *(const float4*)(g_qproj + ((size_t)(b * 2048 + r0 + r)) * 32 + d4 * 4);
            v.x *= scale; v.y *= scale; v.z *= scale; v.w *= scale;
            *(float4*)&As[r * 36 + d4 * 4] = v;
        }
        #pragma unroll
        for (int idx = t; idx < 512; idx += RPE_THREADS) {
            int r = idx >> 3, d4 = idx & 7;
            *(float4*)&Bs[r * 32 + d4 * 4] =
                *(const float4*)(g_kproj + ((size_t)(b * NK + k0 + r)) * 32 + d4 * 4);
        }
        __syncthreads();

        int tr = t & 15;        // r sub-tile (rows tr + 16*i)
        int tk = t >> 4;        // k sub-tile (cols tk*4 + j)
        float acc[4][4];
        #pragma unroll
        for (int i = 0; i < 4; i++)
            #pragma unroll
            for (int j = 0; j < 4; j++) acc[i][j] = 0.f;

        #pragma unroll
        for (int d4 = 0; d4 < 8; d4++) {
            float4 bf[4];
            #pragma unroll
            for (int j = 0; j < 4; j++)
                bf[j] = *(const float4*)&Bs[(tk * 4 + j) * 32 + d4 * 4];
            #pragma unroll
            for (int i = 0; i < 4; i++) {
                float4 a = *(const float4*)&As[(tr + 16 * i) * 36 + d4 * 4];
                #pragma unroll
                for (int j = 0; j < 4; j++)
                    acc[i][j] += a.x * bf[j].x + a.y * bf[j].y + a.z * bf[j].z + a.w * bf[j].w;
            }
        }

        #pragma unroll
        for (int i = 0; i < 4; i++) {
            float4 o = {acc[i][0], acc[i][1], acc[i][2], acc[i][3]};
            *(float4*)&g_qk[((size_t)(b * 2048 + r0 + tr + 16 * i)) * NK + k0 + tk * 4] = o;
        }
    }
}

// -------------------- softmax + AV kernel --------------------
#define SOFT_THREADS 512
#define SMS_RED    (NH * SST)                    // 16448
#define SMS_TOTAL  (SMS_RED + 512)               // 16960 floats
#define PART_STRIDE 264

__global__ void __launch_bounds__(SOFT_THREADS, 2)
k_soft(float* __restrict__ out_attn) {
    extern __shared__ float sms[];
    float* s_scores = sms;
    float* s_red    = sms + SMS_RED;

    int t = threadIdx.x;
    int bq = blockIdx.x;
    int b = bq >> 8, nq = bq & 255;

    // ---- load logits = RPE + QK (float4, k = 4t) + running max ----
    float runmax[NH];
    const float* grp = g_scores + (size_t)bq * NH * NK + 4 * t;
    const float* gqk = g_qk     + (size_t)bq * NH * NK + 4 * t;
    #pragma unroll
    for (int h = 0; h < NH; h++) {
        float4 a = *(const float4*)(grp + h * NK);
        float4 qv = *(const float4*)(gqk + h * NK);
        a.x += qv.x; a.y += qv.y; a.z += qv.z; a.w += qv.w;
        *(float4*)&s_scores[h * SST + 4 * t] = a;
        runmax[h] = fmaxf(fmaxf(a.x, a.y), fmaxf(a.z, a.w));
    }

    // ---- block max ----
    int lane = t & 31, wid = t >> 5;  // 16 warps
    #pragma unroll
    for (int h = 0; h < NH; h++) {
        float v = runmax[h];
        #pragma unroll
        for (int o = 16; o; o >>= 1) v = fmaxf(v, __shfl_xor_sync(0xffffffffu, v, o));
        if (lane == 0) s_red[h * 16 + wid] = v;
    }
    __syncthreads();
    if (t < NH) {
        float v = s_red[t * 16];
        for (int w2 = 1; w2 < 16; w2++) v = fmaxf(v, s_red[t * 16 + w2]);
        s_red[128 + t] = v;
    }
    __syncthreads();

    // ---- exp sweep (float4) ----
    #pragma unroll
    for (int h = 0; h < NH; h++) {
        float mh = s_red[128 + h];
        float4* p = (float4*)&s_scores[h * SST + 4 * t];
        float4 v = *p;
        v.x = __expf(v.x - mh); v.y = __expf(v.y - mh);
        v.z = __expf(v.z - mh); v.w = __expf(v.w - mh);
        *p = v;
        float s = (v.x + v.y) + (v.z + v.w);
        #pragma unroll
        for (int o = 16; o; o >>= 1) s += __shfl_xor_sync(0xffffffffu, s, o);
        if (lane == 0) s_red[h * 16 + wid] = s;
    }
    __syncthreads();
    if (t < NH) {
        float v = 0.f;
        for (int w2 = 0; w2 < 16; w2++) v += s_red[t * 16 + w2];
        s_red[136 + t] = 1.0f / v;
    }
    __syncthreads();

    // ---- normalized attn writeback (float4) ----
    #pragma unroll
    for (int h = 0; h < NH; h++) {
        float r = s_red[136 + h];
        float4 v = *(const float4*)&s_scores[h * SST + 4 * t];
        v.x *= r; v.y *= r; v.z *= r; v.w *= r;
        *(float4*)&out_attn[((size_t)(b * NH + h) * NQ + nq) * NK + 4 * t] = v;
    }

    // ---- AV: thread = (hg 0..1, ks 0..31, dg 0..7), 4 heads/thread ----
    ull acc01[4], acc23[4];
    #pragma unroll
    for (int hh = 0; hh < 4; hh++) { acc01[hh] = 0ull; acc23[hh] = 0ull; }
    int hg  = t >> 8;
    int rem = t & 255;
    int ks  = rem >> 3;          // 0..31, 64 k each
    int dg  = rem & 7;
    {
        const float* vb = g_vproj + (size_t)b * NK * HD + dg * 4;
        int kbase = ks * 64;
        #pragma unroll 1
        for (int kk4 = 0; kk4 < 16; kk4++) {
            int k = kbase + kk4 * 4;
            f4u v0, v1, v2, v3;
            v0.f = *(const float4*)(vb + (k + 0) * HD);
            v1.f = *(const float4*)(vb + (k + 1) * HD);
            v2.f = *(const float4*)(vb + (k + 2) * HD);
            v3.f = *(const float4*)(vb + (k + 3) * HD);
            #pragma unroll
            for (int hh = 0; hh < 4; hh++) {
                int h = hg * 4 + hh;
                float4 p = *(const float4*)&s_scores[h * SST + k];
                ull pp;
                PACK2(pp, p.x, p.x);
                FMA_F32X2(acc01[hh], pp, v0.u[0], acc01[hh]);
                FMA_F32X2(acc23[hh], pp, v0.u[1], acc23[hh]);
                PACK2(pp, p.y, p.y);
                FMA_F32X2(acc01[hh], pp, v1.u[0], acc01[hh]);
                FMA_F32X2(acc23[hh], pp, v1.u[1], acc23[hh]);
                PACK2(pp, p.z, p.z);
                FMA_F32X2(acc01[hh], pp, v2.u[0], acc01[hh]);
                FMA_F32X2(acc23[hh], pp, v2.u[1], acc23[hh]);
                PACK2(pp, p.w, p.w);
                FMA_F32X2(acc01[hh], pp, v3.u[0], acc01[hh]);
                FMA_F32X2(acc23[hh], pp, v3.u[1], acc23[hh]);
            }
        }
    }
    __syncthreads();    // scores now dead — overlay partials

    #pragma unroll
    for (int hh = 0; hh < 4; hh++) {
        int h = hg * 4 + hh;
        u2f lo, hi; lo.u = acc01[hh]; hi.u = acc23[hh];
        float4 o = {lo.f[0], lo.f[1], hi.f[0], hi.f[1]};
        *(float4*)&s_scores[ks * PART_STRIDE + h * 32 + dg * 4] = o;
    }
    __syncthreads();
    if (t < 256) {
        int h = t >> 5;
        float acc = 0.f;
        #pragma unroll 8
        for (int ks2 = 0; ks2 < 32; ks2++) acc += s_scores[ks2 * PART_STRIDE + t];
        acc *= s_red[136 + h];
        g_xmid[bq * DIM + t] = acc;
    }
}

// -------------------- output projection: float4 weights + split-c ------------
// 256 blocks x 256 threads. Block = 2 q rows. Thread = (cq 0..3, jg 0..63).
// Each thread: 64 LDG.128 of w, 8 accumulators (2 rows x 4 cols), smem reduce.
__global__ void k_proj(const float* __restrict__ w, const float* __restrict__ bias,
                       float* __restrict__ out_x) {
    __shared__ float rows[2][DIM];        // 2 KB
    __shared__ float part[4 * 64 * 8];    // 8 KB: [cq][jg][r*4+c]
    int blk = blockIdx.x;                 // b*128 + qpair
    int b = blk >> 7, qbase = (blk & 127) * 2;
    int t = threadIdx.x;                  // 256
    rows[0][t] = g_xmid[((b << 8) + qbase + 0) * DIM + t];
    rows[1][t] = g_xmid[((b << 8) + qbase + 1) * DIM + t];
    __syncthreads();

    int cq = t >> 6;                      // c-quarter 0..3 (64 c each)
    int jg = t & 63;                      // j-group (4 cols each)
    float4 a0 = {0,0,0,0}, a1 = {0,0,0,0};
    const float* wp = w + jg * 4;
    int c0 = cq * 64;
    #pragma unroll 8
    for (int cc = 0; cc < 64; cc++) {
        int c = c0 + cc;
        float4 wv = *(const float4*)(wp + c * DIM);
        float x0 = rows[0][c], x1 = rows[1][c];
        a0.x += x0 * wv.x; a0.y += x0 * wv.y; a0.z += x0 * wv.z; a0.w += x0 * wv.w;
        a1.x += x1 * wv.x; a1.y += x1 * wv.y; a1.z += x1 * wv.z; a1.w += x1 * wv.w;
    }
    float* pp = part + (cq * 64 + jg) * 8;
    *(float4*)pp       = a0;
    *(float4*)(pp + 4) = a1;
    __syncthreads();

    // reduce over cq: 256 threads x 2 rows
    {
        int j = t;                        // output column
        int jg2 = j >> 2, jc = j & 3;
        float bj = bias[j];
        float r0 = bj, r1 = bj;
        #pragma unroll
        for (int q = 0; q < 4; q++) {
            const float* src = part + (q * 64 + jg2) * 8;
            r0 += src[jc];
            r1 += src[4 + jc];
        }
        out_x[((qbase + 0) * BB + b) * DIM + j] = r0;
        out_x[((qbase + 1) * BB + b) * DIM + j] = r1;
    }
}

// -------------------- launch --------------------
extern "C" void kernel_launch(void* const* d_in, const int* in_sizes, int n_in,
                              void* d_out, int out_size) {
    const float* query = (const float*)d_in[0];
    const float* key   = (const float*)d_in[1];
    const float* refpt = (const float*)d_in[2];
    const float* xyz   = (const float*)d_in[4];
    const float* q_w   = (const float*)d_in[5];
    const float* q_b   = (const float*)d_in[6];
    const float* k_w   = (const float*)d_in[7];
    const float* k_b   = (const float*)d_in[8];
    const float* v_w   = (const float*)d_in[9];
    const float* v_b   = (const float*)d_in[10];
    const float* p_w   = (const float*)d_in[11];
    const float* p_b   = (const float*)d_in[12];
    const float* w1    = (const float*)d_in[13];
    const float* b1    = (const float*)d_in[14];
    const float* w2    = (const float*)d_in[15];

    float* out_x    = (float*)d_out;                       // (nQ, B, DIM)
    float* out_attn = (float*)d_out + BB * NQ * DIM;       // (B, NH, nQ, nK)

    const int soft_smem = SMS_TOTAL * (int)sizeof(float);  // 67840 B
    cudaFuncSetAttribute(k_rpeqk, cudaFuncAttributeMaxDynamicSharedMemorySize, RPEQK_SMEM);
    cudaFuncSetAttribute(k_soft,  cudaFuncAttributeMaxDynamicSharedMemorySize, soft_smem);

    k_pre   <<<1536, 256>>>(w1, b1, w2, query, q_w, q_b, key, k_w, k_b, v_w, v_b);
    k_rpeqk <<<1024 + 2048, RPE_THREADS, RPEQK_SMEM>>>(refpt, xyz);
    k_soft  <<<BB * NQ, SOFT_THREADS, soft_smem>>>(out_attn);
    k_proj  <<<BB * NQ / 2, 256>>>(p_w, p_b, out_x);
}